// round 1
// baseline (speedup 1.0000x reference)
#include <cuda_runtime.h>
#include <cuda_bf16.h>
#include <math.h>

// Problem constants
#define BATCH 2
#define SEQ   2048
#define DIM   1024
#define HEADS 16
#define DH    64
#define MTOT  (BATCH*SEQ)          // 4096 rows

// Scratch (allocation-free rule: __device__ globals)
__device__ float g_qkv[(size_t)MTOT * 3 * DIM];   // [4096, 3072]
__device__ float g_attn[(size_t)MTOT * DIM];      // [4096, 1024]

// ---------------------------------------------------------------------------
// SGEMM: C[M,N] = A[M,K] @ B[K,N], all row-major fp32.
// BM=BN=128, BK=8, 256 threads, 8x8 micro-tile. Dims assumed multiples.
// ---------------------------------------------------------------------------
__global__ __launch_bounds__(256) void sgemm128(const float* __restrict__ A,
                                                const float* __restrict__ B,
                                                float* __restrict__ C,
                                                int M, int N, int K) {
    __shared__ float As[8][132];   // transposed A tile, stride 132 => conflict-free transposed stores
    __shared__ float Bs[8][128];

    const int tid = threadIdx.x;
    const int tr  = tid >> 4;      // 0..15 -> rows tr*8..tr*8+7
    const int tc  = tid & 15;      // 0..15 -> cols tc*8..tc*8+7
    const int m0  = blockIdx.y * 128;
    const int n0  = blockIdx.x * 128;

    float acc[8][8];
#pragma unroll
    for (int i = 0; i < 8; i++)
#pragma unroll
        for (int j = 0; j < 8; j++) acc[i][j] = 0.f;

    const int lm  = tid >> 1;          // A loader: row 0..127
    const int lk4 = (tid & 1) * 4;     //           k offset {0,4}
    const int lbk = tid >> 5;          // B loader: k row 0..7
    const int lbn = (tid & 31) * 4;    //           n offset

    for (int k0 = 0; k0 < K; k0 += 8) {
        // load A tile (transposed into smem)
        float4 a4 = *(const float4*)&A[(size_t)(m0 + lm) * K + k0 + lk4];
        As[lk4 + 0][lm] = a4.x;
        As[lk4 + 1][lm] = a4.y;
        As[lk4 + 2][lm] = a4.z;
        As[lk4 + 3][lm] = a4.w;
        // load B tile (natural)
        *(float4*)&Bs[lbk][lbn] = *(const float4*)&B[(size_t)(k0 + lbk) * N + n0 + lbn];
        __syncthreads();

#pragma unroll
        for (int kk = 0; kk < 8; kk++) {
            float ar[8], br[8];
            *(float4*)&ar[0] = *(float4*)&As[kk][tr * 8];
            *(float4*)&ar[4] = *(float4*)&As[kk][tr * 8 + 4];
            *(float4*)&br[0] = *(float4*)&Bs[kk][tc * 8];
            *(float4*)&br[4] = *(float4*)&Bs[kk][tc * 8 + 4];
#pragma unroll
            for (int i = 0; i < 8; i++)
#pragma unroll
                for (int j = 0; j < 8; j++)
                    acc[i][j] = fmaf(ar[i], br[j], acc[i][j]);
        }
        __syncthreads();
    }

#pragma unroll
    for (int i = 0; i < 8; i++) {
        float* crow = &C[(size_t)(m0 + tr * 8 + i) * N + n0 + tc * 8];
        *(float4*)&crow[0] = make_float4(acc[i][0], acc[i][1], acc[i][2], acc[i][3]);
        *(float4*)&crow[4] = make_float4(acc[i][4], acc[i][5], acc[i][6], acc[i][7]);
    }
}

// ---------------------------------------------------------------------------
// Flash attention, fp32, causal + ALiBi (bias = slope * key_pos).
// Block: 64 q-rows for one (b,h). 256 threads = 16x16, 4x4 micro-tiles.
// Smem (dynamic): Qt[64][68] d-major, Kt[64][68] d-major, Vs[64][68], Ps[64][68]
// ---------------------------------------------------------------------------
#define FP_STRIDE 68
#define FLASH_SMEM (4 * 64 * FP_STRIDE * sizeof(float))

__global__ __launch_bounds__(256) void flash_kernel(const float* __restrict__ qkv,
                                                    float* __restrict__ attn_out) {
    extern __shared__ float sm[];
    float* Qt = sm;                        // [d][r]
    float* Kt = Qt + 64 * FP_STRIDE;       // [d][c]
    float* Vs = Kt + 64 * FP_STRIDE;       // [c][dh]
    float* Ps = Vs + 64 * FP_STRIDE;       // [c][r]

    const int qi = blockIdx.x;             // q tile 0..31
    const int bh = blockIdx.y;             // 0..31
    const int b  = bh >> 4;
    const int h  = bh & 15;
    const int tid = threadIdx.x;
    const int tx = tid & 15;               // S cols / dh cols: tx*4..tx*4+3
    const int ty = tid >> 4;               // S rows: ty*4..ty*4+3
    const int q0 = qi * 64;

    const float scale = 0.125f;            // Dh^-0.5
    const float slope = exp2f(-0.5f * (float)(h + 1));

    const float* qbase = qkv + (size_t)(b * SEQ) * (3 * DIM) + h * DH;
    const float* kbase = qbase + DIM;
    const float* vbase = qbase + 2 * DIM;

    // Load Q tile transposed: Qt[d][r]
#pragma unroll
    for (int g = 0; g < 4; g++) {
        int idx = tid + g * 256;
        int d   = idx >> 4;
        int m4  = (idx & 15) * 4;
        float4 t;
        t.x = qbase[(size_t)(q0 + m4 + 0) * (3 * DIM) + d];
        t.y = qbase[(size_t)(q0 + m4 + 1) * (3 * DIM) + d];
        t.z = qbase[(size_t)(q0 + m4 + 2) * (3 * DIM) + d];
        t.w = qbase[(size_t)(q0 + m4 + 3) * (3 * DIM) + d];
        *(float4*)&Qt[d * FP_STRIDE + m4] = t;
    }

    float o[4][4];
    float m_prev[4], l_run[4];
#pragma unroll
    for (int i = 0; i < 4; i++) {
        m_prev[i] = -1e30f;
        l_run[i] = 0.f;
#pragma unroll
        for (int j = 0; j < 4; j++) o[i][j] = 0.f;
    }

    for (int kt = 0; kt <= qi; kt++) {
        const int k0 = kt * 64;
        const bool last = (kt == qi);
        __syncthreads();   // prev iteration's PV reads done before overwrite

        // Load K transposed + V natural
#pragma unroll
        for (int g = 0; g < 4; g++) {
            int idx = tid + g * 256;
            int d   = idx >> 4;
            int m4  = (idx & 15) * 4;
            float4 t;
            t.x = kbase[(size_t)(k0 + m4 + 0) * (3 * DIM) + d];
            t.y = kbase[(size_t)(k0 + m4 + 1) * (3 * DIM) + d];
            t.z = kbase[(size_t)(k0 + m4 + 2) * (3 * DIM) + d];
            t.w = kbase[(size_t)(k0 + m4 + 3) * (3 * DIM) + d];
            *(float4*)&Kt[d * FP_STRIDE + m4] = t;
            // V: row = d index reused as key row, cols = m4 (dh)
            int vm = idx >> 4;
            int d4 = (idx & 15) * 4;
            *(float4*)&Vs[vm * FP_STRIDE + d4] =
                *(const float4*)&vbase[(size_t)(k0 + vm) * (3 * DIM) + d4];
        }
        __syncthreads();

        // S = Q @ K^T  (4x4 per thread)
        float s[4][4];
#pragma unroll
        for (int i = 0; i < 4; i++)
#pragma unroll
            for (int j = 0; j < 4; j++) s[i][j] = 0.f;

#pragma unroll 16
        for (int d = 0; d < 64; d++) {
            float4 aq = *(float4*)&Qt[d * FP_STRIDE + ty * 4];
            float4 bk = *(float4*)&Kt[d * FP_STRIDE + tx * 4];
            float ar[4] = {aq.x, aq.y, aq.z, aq.w};
            float br[4] = {bk.x, bk.y, bk.z, bk.w};
#pragma unroll
            for (int i = 0; i < 4; i++)
#pragma unroll
                for (int j = 0; j < 4; j++)
                    s[i][j] = fmaf(ar[i], br[j], s[i][j]);
        }

        // scale + ALiBi bias + causal mask (diagonal tile only)
#pragma unroll
        for (int i = 0; i < 4; i++) {
#pragma unroll
            for (int j = 0; j < 4; j++) {
                int kpos = k0 + tx * 4 + j;
                float v = s[i][j] * scale + slope * (float)kpos;
                if (last && kpos > (q0 + ty * 4 + i)) v = -1e30f;
                s[i][j] = v;
            }
        }

        // online softmax: row max over 64 cols (4 local + 16-lane shfl reduce)
        float rmax[4], rsum[4];
#pragma unroll
        for (int i = 0; i < 4; i++) {
            float m = fmaxf(fmaxf(s[i][0], s[i][1]), fmaxf(s[i][2], s[i][3]));
#pragma unroll
            for (int off = 8; off >= 1; off >>= 1)
                m = fmaxf(m, __shfl_xor_sync(0xffffffffu, m, off));
            float mn = fmaxf(m_prev[i], m);
            float sum = 0.f;
#pragma unroll
            for (int j = 0; j < 4; j++) {
                float p = __expf(s[i][j] - mn);
                s[i][j] = p;
                sum += p;
            }
#pragma unroll
            for (int off = 8; off >= 1; off >>= 1)
                sum += __shfl_xor_sync(0xffffffffu, sum, off);
            float alpha = __expf(m_prev[i] - mn);
            l_run[i] = l_run[i] * alpha + sum;
            m_prev[i] = mn;
            rmax[i] = mn; (void)rmax; rsum[i] = sum; (void)rsum;
#pragma unroll
            for (int j = 0; j < 4; j++) o[i][j] *= alpha;
        }

        // write P transposed: Ps[c][r]
#pragma unroll
        for (int i = 0; i < 4; i++)
#pragma unroll
            for (int j = 0; j < 4; j++)
                Ps[(tx * 4 + j) * FP_STRIDE + ty * 4 + i] = s[i][j];
        __syncthreads();

        // O += P @ V
#pragma unroll 8
        for (int c = 0; c < 64; c++) {
            float4 pv = *(float4*)&Ps[c * FP_STRIDE + ty * 4];
            float4 vv = *(float4*)&Vs[c * FP_STRIDE + tx * 4];
            float pr[4] = {pv.x, pv.y, pv.z, pv.w};
            float vr[4] = {vv.x, vv.y, vv.z, vv.w};
#pragma unroll
            for (int i = 0; i < 4; i++)
#pragma unroll
                for (int j = 0; j < 4; j++)
                    o[i][j] = fmaf(pr[i], vr[j], o[i][j]);
        }
    }

    // epilogue: normalize and store to [b, n, h*64+dh]
#pragma unroll
    for (int i = 0; i < 4; i++) {
        float inv = 1.f / l_run[i];
        int row = q0 + ty * 4 + i;
        float4 r = make_float4(o[i][0] * inv, o[i][1] * inv, o[i][2] * inv, o[i][3] * inv);
        *(float4*)&attn_out[(size_t)(b * SEQ + row) * DIM + h * DH + tx * 4] = r;
    }
}

// ---------------------------------------------------------------------------
extern "C" void kernel_launch(void* const* d_in, const int* in_sizes, int n_in,
                              void* d_out, int out_size) {
    const float* x      = (const float*)d_in[0];   // [2,2048,1024]
    const float* w_qkv  = (const float*)d_in[1];   // [1024,3072]
    const float* w_proj = (const float*)d_in[2];   // [1024,1024]
    float* out = (float*)d_out;                    // [2,2048,1024]

    float *qkv_ptr, *attn_ptr;
    cudaGetSymbolAddress((void**)&qkv_ptr, g_qkv);
    cudaGetSymbolAddress((void**)&attn_ptr, g_attn);

    cudaFuncSetAttribute(flash_kernel, cudaFuncAttributeMaxDynamicSharedMemorySize,
                         (int)FLASH_SMEM);

    // 1) qkv = x @ w_qkv    [4096,1024]@[1024,3072]
    sgemm128<<<dim3(3 * DIM / 128, MTOT / 128), 256>>>(x, w_qkv, qkv_ptr, MTOT, 3 * DIM, DIM);

    // 2) attention
    flash_kernel<<<dim3(SEQ / 64, BATCH * HEADS), 256, FLASH_SMEM>>>(qkv_ptr, attn_ptr);

    // 3) out = attn @ w_proj [4096,1024]@[1024,1024]
    sgemm128<<<dim3(DIM / 128, MTOT / 128), 256>>>(attn_ptr, w_proj, out, MTOT, DIM, DIM);
}

// round 2
// speedup vs baseline: 1.4329x; 1.4329x over previous
#include <cuda_runtime.h>
#include <cuda_bf16.h>
#include <math.h>
#include <stdint.h>

// Problem constants
#define BATCH 2
#define SEQ   2048
#define DIM   1024
#define HEADS 16
#define DH    64
#define MTOT  (BATCH*SEQ)          // 4096 rows

// Scratch (allocation-free rule: __device__ globals)
__device__ float g_qkv[(size_t)MTOT * 3 * DIM];   // [4096, 3072]
__device__ float g_attn[(size_t)MTOT * DIM];      // [4096, 1024]

// ---------------------------------------------------------------------------
// TF32 tensor-core GEMM: C[M,N] = A[M,K] @ B[K,N], row-major fp32 in/out.
// BM=128, BN=128, BK=16, 256 threads = 8 warps (4m x 2n), warp tile 32x64.
// mma.sync.m16n8k8.tf32, inputs rounded with cvt.rna (unbiased).
// Smem tiles stored K-major with stride 20 -> conflict-free fragment loads.
// ---------------------------------------------------------------------------
#define GBM 128
#define GBN 128
#define GBK 16
#define GSTRIDE 20

__device__ __forceinline__ uint32_t f2tf32(float v) {
    uint32_t o;
    asm("cvt.rna.tf32.f32 %0, %1;" : "=r"(o) : "f"(v));
    return o;
}

__device__ __forceinline__ void mma_tf32(float c[4], const uint32_t a[4], const uint32_t b[2]) {
    asm volatile(
        "mma.sync.aligned.m16n8k8.row.col.f32.tf32.tf32.f32 "
        "{%0,%1,%2,%3}, {%4,%5,%6,%7}, {%8,%9}, {%0,%1,%2,%3};"
        : "+f"(c[0]), "+f"(c[1]), "+f"(c[2]), "+f"(c[3])
        : "r"(a[0]), "r"(a[1]), "r"(a[2]), "r"(a[3]), "r"(b[0]), "r"(b[1]));
}

__global__ __launch_bounds__(256) void sgemm_tf32(const float* __restrict__ A,
                                                  const float* __restrict__ B,
                                                  float* __restrict__ C,
                                                  int M, int N, int K) {
    // double-buffered tiles, K-major with pad
    __shared__ uint32_t As[2][GBM][GSTRIDE];   // [m][k]
    __shared__ uint32_t Bs[2][GBN][GSTRIDE];   // [n][k]

    const int tid  = threadIdx.x;
    const int lane = tid & 31;
    const int wid  = tid >> 5;
    const int wm   = wid & 3;        // 0..3 -> m offset wm*32
    const int wn   = wid >> 2;       // 0..1 -> n offset wn*64
    const int g    = lane >> 2;      // group 0..7
    const int q    = lane & 3;       // quad  0..3

    const int m0 = blockIdx.y * GBM;
    const int n0 = blockIdx.x * GBN;

    // loader indices
    const int a_row  = tid >> 2;          // 0..63 (+64)
    const int a_col4 = (tid & 3) * 4;     // 0,4,8,12
    const int b_k    = tid >> 4;          // 0..15
    const int b_n4   = (tid & 15) * 4;    // 0..60 (+64)

    float acc[2][8][4];
#pragma unroll
    for (int i = 0; i < 2; i++)
#pragma unroll
        for (int j = 0; j < 8; j++)
#pragma unroll
            for (int r = 0; r < 4; r++) acc[i][j][r] = 0.f;

    const int ntiles = K / GBK;

    // ---- load tile 0 ----
    float4 ra[2], rb[2];
#pragma unroll
    for (int i = 0; i < 2; i++) {
        ra[i] = *(const float4*)&A[(size_t)(m0 + a_row + 64 * i) * K + a_col4];
        rb[i] = *(const float4*)&B[(size_t)b_k * N + n0 + b_n4 + 64 * i];
    }
#pragma unroll
    for (int i = 0; i < 2; i++) {
        int r = a_row + 64 * i;
        As[0][r][a_col4 + 0] = f2tf32(ra[i].x);
        As[0][r][a_col4 + 1] = f2tf32(ra[i].y);
        As[0][r][a_col4 + 2] = f2tf32(ra[i].z);
        As[0][r][a_col4 + 3] = f2tf32(ra[i].w);
        int n = b_n4 + 64 * i;
        Bs[0][n + 0][b_k] = f2tf32(rb[i].x);
        Bs[0][n + 1][b_k] = f2tf32(rb[i].y);
        Bs[0][n + 2][b_k] = f2tf32(rb[i].z);
        Bs[0][n + 3][b_k] = f2tf32(rb[i].w);
    }
    __syncthreads();

    for (int kt = 0; kt < ntiles; kt++) {
        const int cur = kt & 1, nxt = cur ^ 1;
        const bool more = (kt + 1 < ntiles);

        // prefetch next tile from gmem
        if (more) {
            int k0 = (kt + 1) * GBK;
#pragma unroll
            for (int i = 0; i < 2; i++) {
                ra[i] = *(const float4*)&A[(size_t)(m0 + a_row + 64 * i) * K + k0 + a_col4];
                rb[i] = *(const float4*)&B[(size_t)(k0 + b_k) * N + n0 + b_n4 + 64 * i];
            }
        }

        // compute current tile: 2 k-slices of 8
#pragma unroll
        for (int ks = 0; ks < 2; ks++) {
            uint32_t afr[2][4];
#pragma unroll
            for (int mt = 0; mt < 2; mt++) {
                int rb0 = wm * 32 + mt * 16;
                afr[mt][0] = As[cur][rb0 + g][ks * 8 + q];
                afr[mt][1] = As[cur][rb0 + g + 8][ks * 8 + q];
                afr[mt][2] = As[cur][rb0 + g][ks * 8 + q + 4];
                afr[mt][3] = As[cur][rb0 + g + 8][ks * 8 + q + 4];
            }
#pragma unroll
            for (int nt = 0; nt < 8; nt++) {
                int nb = wn * 64 + nt * 8;
                uint32_t bfr[2];
                bfr[0] = Bs[cur][nb + g][ks * 8 + q];
                bfr[1] = Bs[cur][nb + g][ks * 8 + q + 4];
                mma_tf32(acc[0][nt], afr[0], bfr);
                mma_tf32(acc[1][nt], afr[1], bfr);
            }
        }

        // store prefetched tile into other buffer
        if (more) {
#pragma unroll
            for (int i = 0; i < 2; i++) {
                int r = a_row + 64 * i;
                As[nxt][r][a_col4 + 0] = f2tf32(ra[i].x);
                As[nxt][r][a_col4 + 1] = f2tf32(ra[i].y);
                As[nxt][r][a_col4 + 2] = f2tf32(ra[i].z);
                As[nxt][r][a_col4 + 3] = f2tf32(ra[i].w);
                int n = b_n4 + 64 * i;
                Bs[nxt][n + 0][b_k] = f2tf32(rb[i].x);
                Bs[nxt][n + 1][b_k] = f2tf32(rb[i].y);
                Bs[nxt][n + 2][b_k] = f2tf32(rb[i].z);
                Bs[nxt][n + 3][b_k] = f2tf32(rb[i].w);
            }
        }
        __syncthreads();
    }

    // epilogue
#pragma unroll
    for (int mt = 0; mt < 2; mt++) {
        int r0 = m0 + wm * 32 + mt * 16 + g;
#pragma unroll
        for (int nt = 0; nt < 8; nt++) {
            int c0 = n0 + wn * 64 + nt * 8 + q * 2;
            *(float2*)&C[(size_t)r0 * N + c0]       = make_float2(acc[mt][nt][0], acc[mt][nt][1]);
            *(float2*)&C[(size_t)(r0 + 8) * N + c0] = make_float2(acc[mt][nt][2], acc[mt][nt][3]);
        }
    }
}

// ---------------------------------------------------------------------------
// Flash attention, fp32, causal + ALiBi (bias = slope * key_pos).
// Block: 64 q-rows for one (b,h). 256 threads = 16x16, 4x4 micro-tiles.
// ---------------------------------------------------------------------------
#define FP_STRIDE 68
#define FLASH_SMEM (4 * 64 * FP_STRIDE * sizeof(float))

__global__ __launch_bounds__(256) void flash_kernel(const float* __restrict__ qkv,
                                                    float* __restrict__ attn_out) {
    extern __shared__ float sm[];
    float* Qt = sm;                        // [d][r]
    float* Kt = Qt + 64 * FP_STRIDE;       // [d][c]
    float* Vs = Kt + 64 * FP_STRIDE;       // [c][dh]
    float* Ps = Vs + 64 * FP_STRIDE;       // [c][r]

    const int qi = blockIdx.x;
    const int bh = blockIdx.y;
    const int b  = bh >> 4;
    const int h  = bh & 15;
    const int tid = threadIdx.x;
    const int tx = tid & 15;
    const int ty = tid >> 4;
    const int q0 = qi * 64;

    const float scale = 0.125f;
    const float slope = exp2f(-0.5f * (float)(h + 1));

    const float* qbase = qkv + (size_t)(b * SEQ) * (3 * DIM) + h * DH;
    const float* kbase = qbase + DIM;
    const float* vbase = qbase + 2 * DIM;

#pragma unroll
    for (int g = 0; g < 4; g++) {
        int idx = tid + g * 256;
        int d   = idx >> 4;
        int m4  = (idx & 15) * 4;
        float4 t;
        t.x = qbase[(size_t)(q0 + m4 + 0) * (3 * DIM) + d];
        t.y = qbase[(size_t)(q0 + m4 + 1) * (3 * DIM) + d];
        t.z = qbase[(size_t)(q0 + m4 + 2) * (3 * DIM) + d];
        t.w = qbase[(size_t)(q0 + m4 + 3) * (3 * DIM) + d];
        *(float4*)&Qt[d * FP_STRIDE + m4] = t;
    }

    float o[4][4];
    float m_prev[4], l_run[4];
#pragma unroll
    for (int i = 0; i < 4; i++) {
        m_prev[i] = -1e30f;
        l_run[i] = 0.f;
#pragma unroll
        for (int j = 0; j < 4; j++) o[i][j] = 0.f;
    }

    for (int kt = 0; kt <= qi; kt++) {
        const int k0 = kt * 64;
        const bool last = (kt == qi);
        __syncthreads();

#pragma unroll
        for (int g = 0; g < 4; g++) {
            int idx = tid + g * 256;
            int d   = idx >> 4;
            int m4  = (idx & 15) * 4;
            float4 t;
            t.x = kbase[(size_t)(k0 + m4 + 0) * (3 * DIM) + d];
            t.y = kbase[(size_t)(k0 + m4 + 1) * (3 * DIM) + d];
            t.z = kbase[(size_t)(k0 + m4 + 2) * (3 * DIM) + d];
            t.w = kbase[(size_t)(k0 + m4 + 3) * (3 * DIM) + d];
            *(float4*)&Kt[d * FP_STRIDE + m4] = t;
            int vm = idx >> 4;
            int d4 = (idx & 15) * 4;
            *(float4*)&Vs[vm * FP_STRIDE + d4] =
                *(const float4*)&vbase[(size_t)(k0 + vm) * (3 * DIM) + d4];
        }
        __syncthreads();

        float s[4][4];
#pragma unroll
        for (int i = 0; i < 4; i++)
#pragma unroll
            for (int j = 0; j < 4; j++) s[i][j] = 0.f;

#pragma unroll 16
        for (int d = 0; d < 64; d++) {
            float4 aq = *(float4*)&Qt[d * FP_STRIDE + ty * 4];
            float4 bk = *(float4*)&Kt[d * FP_STRIDE + tx * 4];
            float ar[4] = {aq.x, aq.y, aq.z, aq.w};
            float br[4] = {bk.x, bk.y, bk.z, bk.w};
#pragma unroll
            for (int i = 0; i < 4; i++)
#pragma unroll
                for (int j = 0; j < 4; j++)
                    s[i][j] = fmaf(ar[i], br[j], s[i][j]);
        }

#pragma unroll
        for (int i = 0; i < 4; i++) {
#pragma unroll
            for (int j = 0; j < 4; j++) {
                int kpos = k0 + tx * 4 + j;
                float v = s[i][j] * scale + slope * (float)kpos;
                if (last && kpos > (q0 + ty * 4 + i)) v = -1e30f;
                s[i][j] = v;
            }
        }

#pragma unroll
        for (int i = 0; i < 4; i++) {
            float m = fmaxf(fmaxf(s[i][0], s[i][1]), fmaxf(s[i][2], s[i][3]));
#pragma unroll
            for (int off = 8; off >= 1; off >>= 1)
                m = fmaxf(m, __shfl_xor_sync(0xffffffffu, m, off));
            float mn = fmaxf(m_prev[i], m);
            float sum = 0.f;
#pragma unroll
            for (int j = 0; j < 4; j++) {
                float p = __expf(s[i][j] - mn);
                s[i][j] = p;
                sum += p;
            }
#pragma unroll
            for (int off = 8; off >= 1; off >>= 1)
                sum += __shfl_xor_sync(0xffffffffu, sum, off);
            float alpha = __expf(m_prev[i] - mn);
            l_run[i] = l_run[i] * alpha + sum;
            m_prev[i] = mn;
#pragma unroll
            for (int j = 0; j < 4; j++) o[i][j] *= alpha;
        }

#pragma unroll
        for (int i = 0; i < 4; i++)
#pragma unroll
            for (int j = 0; j < 4; j++)
                Ps[(tx * 4 + j) * FP_STRIDE + ty * 4 + i] = s[i][j];
        __syncthreads();

#pragma unroll 8
        for (int c = 0; c < 64; c++) {
            float4 pv = *(float4*)&Ps[c * FP_STRIDE + ty * 4];
            float4 vv = *(float4*)&Vs[c * FP_STRIDE + tx * 4];
            float pr[4] = {pv.x, pv.y, pv.z, pv.w};
            float vr[4] = {vv.x, vv.y, vv.z, vv.w};
#pragma unroll
            for (int i = 0; i < 4; i++)
#pragma unroll
                for (int j = 0; j < 4; j++)
                    o[i][j] = fmaf(pr[i], vr[j], o[i][j]);
        }
    }

#pragma unroll
    for (int i = 0; i < 4; i++) {
        float inv = 1.f / l_run[i];
        int row = q0 + ty * 4 + i;
        float4 r = make_float4(o[i][0] * inv, o[i][1] * inv, o[i][2] * inv, o[i][3] * inv);
        *(float4*)&attn_out[(size_t)(b * SEQ + row) * DIM + h * DH + tx * 4] = r;
    }
}

// ---------------------------------------------------------------------------
extern "C" void kernel_launch(void* const* d_in, const int* in_sizes, int n_in,
                              void* d_out, int out_size) {
    const float* x      = (const float*)d_in[0];   // [2,2048,1024]
    const float* w_qkv  = (const float*)d_in[1];   // [1024,3072]
    const float* w_proj = (const float*)d_in[2];   // [1024,1024]
    float* out = (float*)d_out;                    // [2,2048,1024]

    float *qkv_ptr, *attn_ptr;
    cudaGetSymbolAddress((void**)&qkv_ptr, g_qkv);
    cudaGetSymbolAddress((void**)&attn_ptr, g_attn);

    cudaFuncSetAttribute(flash_kernel, cudaFuncAttributeMaxDynamicSharedMemorySize,
                         (int)FLASH_SMEM);

    // 1) qkv = x @ w_qkv    [4096,1024]@[1024,3072]
    sgemm_tf32<<<dim3(3 * DIM / GBN, MTOT / GBM), 256>>>(x, w_qkv, qkv_ptr, MTOT, 3 * DIM, DIM);

    // 2) attention
    flash_kernel<<<dim3(SEQ / 64, BATCH * HEADS), 256, FLASH_SMEM>>>(qkv_ptr, attn_ptr);

    // 3) out = attn @ w_proj [4096,1024]@[1024,1024]
    sgemm_tf32<<<dim3(DIM / GBN, MTOT / GBM), 256>>>(attn_ptr, w_proj, out, MTOT, DIM, DIM);
}

// round 3
// speedup vs baseline: 2.7708x; 1.9337x over previous
#include <cuda_runtime.h>
#include <cuda_bf16.h>
#include <math.h>
#include <stdint.h>

// Problem constants
#define BATCH 2
#define SEQ   2048
#define DIM   1024
#define HEADS 16
#define DH    64
#define MTOT  (BATCH*SEQ)          // 4096 rows

// Scratch (allocation-free rule: __device__ globals)
__device__ float g_qkv[(size_t)MTOT * 3 * DIM];   // [4096, 3072]
__device__ float g_attn[(size_t)MTOT * DIM];      // [4096, 1024]

__device__ __forceinline__ uint32_t f2tf32(float v) {
    uint32_t o;
    asm("cvt.rna.tf32.f32 %0, %1;" : "=r"(o) : "f"(v));
    return o;
}

__device__ __forceinline__ void mma_tf32(float c[4], const uint32_t a[4], const uint32_t b[2]) {
    asm volatile(
        "mma.sync.aligned.m16n8k8.row.col.f32.tf32.tf32.f32 "
        "{%0,%1,%2,%3}, {%4,%5,%6,%7}, {%8,%9}, {%0,%1,%2,%3};"
        : "+f"(c[0]), "+f"(c[1]), "+f"(c[2]), "+f"(c[3])
        : "r"(a[0]), "r"(a[1]), "r"(a[2]), "r"(a[3]), "r"(b[0]), "r"(b[1]));
}

// ---------------------------------------------------------------------------
// TF32 tensor-core GEMM (unchanged from R1): C = A @ B, row-major fp32.
// ---------------------------------------------------------------------------
#define GBM 128
#define GBN 128
#define GBK 16
#define GSTRIDE 20

__global__ __launch_bounds__(256) void sgemm_tf32(const float* __restrict__ A,
                                                  const float* __restrict__ B,
                                                  float* __restrict__ C,
                                                  int M, int N, int K) {
    __shared__ uint32_t As[2][GBM][GSTRIDE];
    __shared__ uint32_t Bs[2][GBN][GSTRIDE];

    const int tid  = threadIdx.x;
    const int lane = tid & 31;
    const int wid  = tid >> 5;
    const int wm   = wid & 3;
    const int wn   = wid >> 2;
    const int g    = lane >> 2;
    const int q    = lane & 3;

    const int m0 = blockIdx.y * GBM;
    const int n0 = blockIdx.x * GBN;

    const int a_row  = tid >> 2;
    const int a_col4 = (tid & 3) * 4;
    const int b_k    = tid >> 4;
    const int b_n4   = (tid & 15) * 4;

    float acc[2][8][4];
#pragma unroll
    for (int i = 0; i < 2; i++)
#pragma unroll
        for (int j = 0; j < 8; j++)
#pragma unroll
            for (int r = 0; r < 4; r++) acc[i][j][r] = 0.f;

    const int ntiles = K / GBK;

    float4 ra[2], rb[2];
#pragma unroll
    for (int i = 0; i < 2; i++) {
        ra[i] = *(const float4*)&A[(size_t)(m0 + a_row + 64 * i) * K + a_col4];
        rb[i] = *(const float4*)&B[(size_t)b_k * N + n0 + b_n4 + 64 * i];
    }
#pragma unroll
    for (int i = 0; i < 2; i++) {
        int r = a_row + 64 * i;
        As[0][r][a_col4 + 0] = f2tf32(ra[i].x);
        As[0][r][a_col4 + 1] = f2tf32(ra[i].y);
        As[0][r][a_col4 + 2] = f2tf32(ra[i].z);
        As[0][r][a_col4 + 3] = f2tf32(ra[i].w);
        int n = b_n4 + 64 * i;
        Bs[0][n + 0][b_k] = f2tf32(rb[i].x);
        Bs[0][n + 1][b_k] = f2tf32(rb[i].y);
        Bs[0][n + 2][b_k] = f2tf32(rb[i].z);
        Bs[0][n + 3][b_k] = f2tf32(rb[i].w);
    }
    __syncthreads();

    for (int kt = 0; kt < ntiles; kt++) {
        const int cur = kt & 1, nxt = cur ^ 1;
        const bool more = (kt + 1 < ntiles);

        if (more) {
            int k0 = (kt + 1) * GBK;
#pragma unroll
            for (int i = 0; i < 2; i++) {
                ra[i] = *(const float4*)&A[(size_t)(m0 + a_row + 64 * i) * K + k0 + a_col4];
                rb[i] = *(const float4*)&B[(size_t)(k0 + b_k) * N + n0 + b_n4 + 64 * i];
            }
        }

#pragma unroll
        for (int ks = 0; ks < 2; ks++) {
            uint32_t afr[2][4];
#pragma unroll
            for (int mt = 0; mt < 2; mt++) {
                int rb0 = wm * 32 + mt * 16;
                afr[mt][0] = As[cur][rb0 + g][ks * 8 + q];
                afr[mt][1] = As[cur][rb0 + g + 8][ks * 8 + q];
                afr[mt][2] = As[cur][rb0 + g][ks * 8 + q + 4];
                afr[mt][3] = As[cur][rb0 + g + 8][ks * 8 + q + 4];
            }
#pragma unroll
            for (int nt = 0; nt < 8; nt++) {
                int nb = wn * 64 + nt * 8;
                uint32_t bfr[2];
                bfr[0] = Bs[cur][nb + g][ks * 8 + q];
                bfr[1] = Bs[cur][nb + g][ks * 8 + q + 4];
                mma_tf32(acc[0][nt], afr[0], bfr);
                mma_tf32(acc[1][nt], afr[1], bfr);
            }
        }

        if (more) {
#pragma unroll
            for (int i = 0; i < 2; i++) {
                int r = a_row + 64 * i;
                As[nxt][r][a_col4 + 0] = f2tf32(ra[i].x);
                As[nxt][r][a_col4 + 1] = f2tf32(ra[i].y);
                As[nxt][r][a_col4 + 2] = f2tf32(ra[i].z);
                As[nxt][r][a_col4 + 3] = f2tf32(ra[i].w);
                int n = b_n4 + 64 * i;
                Bs[nxt][n + 0][b_k] = f2tf32(rb[i].x);
                Bs[nxt][n + 1][b_k] = f2tf32(rb[i].y);
                Bs[nxt][n + 2][b_k] = f2tf32(rb[i].z);
                Bs[nxt][n + 3][b_k] = f2tf32(rb[i].w);
            }
        }
        __syncthreads();
    }

#pragma unroll
    for (int mt = 0; mt < 2; mt++) {
        int r0 = m0 + wm * 32 + mt * 16 + g;
#pragma unroll
        for (int nt = 0; nt < 8; nt++) {
            int c0 = n0 + wn * 64 + nt * 8 + q * 2;
            *(float2*)&C[(size_t)r0 * N + c0]       = make_float2(acc[mt][nt][0], acc[mt][nt][1]);
            *(float2*)&C[(size_t)(r0 + 8) * N + c0] = make_float2(acc[mt][nt][2], acc[mt][nt][3]);
        }
    }
}

// ---------------------------------------------------------------------------
// Flash attention with TF32 mma.sync tensor cores.
// Block: 128 threads (4 warps) handles the q-tile PAIR {qi, 15-qi} for one
// (b,h) -> perfectly balanced causal work (34 key-tiles per block).
// Each warp: 32 q-rows x 64 keys. Softmax in mma C-fragment layout, base-2.
// Smem: Qs[128][68] tf32, Ks[64][68] (key-major), Vs[64][68] (d-major,
// i.e. V transposed), Ps[4][32][68] per-warp P tiles.
// ---------------------------------------------------------------------------
#define FSTR 68
#define NQT  (SEQ/128)   // 16 q-tiles
#define FLASH_SMEM ((128*FSTR + 64*FSTR + 64*FSTR + 4*32*FSTR) * 4)

__global__ __launch_bounds__(128) void flash_mma(const float* __restrict__ qkv,
                                                 float* __restrict__ attn_out) {
    extern __shared__ uint32_t sm[];
    uint32_t* Qs = sm;                       // [qrow][d]
    uint32_t* Ks = Qs + 128 * FSTR;          // [key][d]
    uint32_t* Vs = Ks + 64 * FSTR;           // [d][key]  (V^T)
    uint32_t* Ps = Vs + 64 * FSTR;           // [warp][row][key]

    const int tid  = threadIdx.x;
    const int lane = tid & 31;
    const int w    = tid >> 5;
    const int g    = lane >> 2;
    const int q    = lane & 3;

    const int bh = blockIdx.y;
    const int b  = bh >> 4;
    const int h  = bh & 15;

    const float LOG2E  = 1.44269504088896f;
    const float scale2 = 0.125f * LOG2E;                       // Dh^-0.5 * log2(e)
    const float slope2 = exp2f(-0.5f * (float)(h + 1)) * LOG2E;

    const float* qb = qkv + (size_t)b * SEQ * (3 * DIM) + h * DH;
    const float* kb = qb + DIM;
    const float* vb = qb + 2 * DIM;

    uint32_t* Pw = Ps + w * 32 * FSTR;

#pragma unroll 1
    for (int half = 0; half < 2; half++) {
        const int qi = half ? (NQT - 1 - blockIdx.x) : blockIdx.x;
        const int q0 = qi * 128;

        __syncthreads();   // Qs/Ks/Vs reuse across halves

        // ---- load Q tile (rows q0..q0+127) as tf32, [row][d] ----
        {
            int r  = tid >> 4;
            int d4 = (tid & 15) * 4;
#pragma unroll
            for (int it = 0; it < 16; it++, r += 8) {
                float4 v = *(const float4*)&qb[(size_t)(q0 + r) * (3 * DIM) + d4];
                *(uint4*)&Qs[r * FSTR + d4] =
                    make_uint4(f2tf32(v.x), f2tf32(v.y), f2tf32(v.z), f2tf32(v.w));
            }
        }

        // per-row state (rows: mt*16+g and mt*16+g+8 within warp tile)
        float o[2][8][4];
        float mprev[2][2], lrun[2][2];
#pragma unroll
        for (int mt = 0; mt < 2; mt++) {
            mprev[mt][0] = mprev[mt][1] = -1e30f;
            lrun[mt][0]  = lrun[mt][1]  = 0.f;
#pragma unroll
            for (int nt = 0; nt < 8; nt++)
#pragma unroll
                for (int r = 0; r < 4; r++) o[mt][nt][r] = 0.f;
        }

        const int nkt = 2 * qi + 2;
        const int wrow_min = q0 + w * 32;       // warp's first q-row
        const int wrow_max = wrow_min + 31;

        for (int kt = 0; kt < nkt; kt++) {
            const int k0 = kt * 64;
            __syncthreads();   // previous tile's PV reads done

            // ---- load K [key][d] and V^T [d][key] ----
            {
                int key = tid >> 4;
                int d4  = (tid & 15) * 4;
#pragma unroll
                for (int it = 0; it < 8; it++, key += 8) {
                    float4 kv = *(const float4*)&kb[(size_t)(k0 + key) * (3 * DIM) + d4];
                    *(uint4*)&Ks[key * FSTR + d4] =
                        make_uint4(f2tf32(kv.x), f2tf32(kv.y), f2tf32(kv.z), f2tf32(kv.w));
                    float4 vv = *(const float4*)&vb[(size_t)(k0 + key) * (3 * DIM) + d4];
                    Vs[(d4 + 0) * FSTR + key] = f2tf32(vv.x);
                    Vs[(d4 + 1) * FSTR + key] = f2tf32(vv.y);
                    Vs[(d4 + 2) * FSTR + key] = f2tf32(vv.z);
                    Vs[(d4 + 3) * FSTR + key] = f2tf32(vv.w);
                }
            }
            __syncthreads();

            // warp-uniform skip: entire tile above the diagonal for this warp
            if (k0 > wrow_max) continue;

            // ---- S = Q @ K^T ----
            float s[2][8][4];
#pragma unroll
            for (int mt = 0; mt < 2; mt++)
#pragma unroll
                for (int nt = 0; nt < 8; nt++)
#pragma unroll
                    for (int r = 0; r < 4; r++) s[mt][nt][r] = 0.f;

#pragma unroll
            for (int ks = 0; ks < 8; ks++) {
                uint32_t afr[2][4];
#pragma unroll
                for (int mt = 0; mt < 2; mt++) {
                    int rb0 = w * 32 + mt * 16;
                    afr[mt][0] = Qs[(rb0 + g)     * FSTR + ks * 8 + q];
                    afr[mt][1] = Qs[(rb0 + g + 8) * FSTR + ks * 8 + q];
                    afr[mt][2] = Qs[(rb0 + g)     * FSTR + ks * 8 + q + 4];
                    afr[mt][3] = Qs[(rb0 + g + 8) * FSTR + ks * 8 + q + 4];
                }
#pragma unroll
                for (int nt = 0; nt < 8; nt++) {
                    uint32_t bfr[2];
                    bfr[0] = Ks[(nt * 8 + g) * FSTR + ks * 8 + q];
                    bfr[1] = Ks[(nt * 8 + g) * FSTR + ks * 8 + q + 4];
                    mma_tf32(s[0][nt], afr[0], bfr);
                    mma_tf32(s[1][nt], afr[1], bfr);
                }
            }

            // ---- bias + mask + online softmax (base-2 domain) ----
            const bool need_mask = (k0 + 63 > wrow_min);
#pragma unroll
            for (int mt = 0; mt < 2; mt++) {
                const int r0 = wrow_min + mt * 16 + g;
                const int r1 = r0 + 8;
                float mx0 = -1e30f, mx1 = -1e30f;
#pragma unroll
                for (int nt = 0; nt < 8; nt++) {
#pragma unroll
                    for (int jj = 0; jj < 2; jj++) {
                        int col = k0 + nt * 8 + q * 2 + jj;
                        float bias = slope2 * (float)col;
                        float v0 = fmaf(s[mt][nt][jj],     scale2, bias);
                        float v1 = fmaf(s[mt][nt][2 + jj], scale2, bias);
                        if (need_mask) {
                            if (col > r0) v0 = -1e30f;
                            if (col > r1) v1 = -1e30f;
                        }
                        s[mt][nt][jj]     = v0;
                        s[mt][nt][2 + jj] = v1;
                        mx0 = fmaxf(mx0, v0);
                        mx1 = fmaxf(mx1, v1);
                    }
                }
                mx0 = fmaxf(mx0, __shfl_xor_sync(0xffffffffu, mx0, 1));
                mx0 = fmaxf(mx0, __shfl_xor_sync(0xffffffffu, mx0, 2));
                mx1 = fmaxf(mx1, __shfl_xor_sync(0xffffffffu, mx1, 1));
                mx1 = fmaxf(mx1, __shfl_xor_sync(0xffffffffu, mx1, 2));

                float mn0 = fmaxf(mprev[mt][0], mx0);
                float mn1 = fmaxf(mprev[mt][1], mx1);
                float sum0 = 0.f, sum1 = 0.f;
#pragma unroll
                for (int nt = 0; nt < 8; nt++) {
#pragma unroll
                    for (int jj = 0; jj < 2; jj++) {
                        float p0 = exp2f(s[mt][nt][jj]     - mn0);
                        float p1 = exp2f(s[mt][nt][2 + jj] - mn1);
                        s[mt][nt][jj]     = p0;
                        s[mt][nt][2 + jj] = p1;
                        sum0 += p0;
                        sum1 += p1;
                    }
                }
                sum0 += __shfl_xor_sync(0xffffffffu, sum0, 1);
                sum0 += __shfl_xor_sync(0xffffffffu, sum0, 2);
                sum1 += __shfl_xor_sync(0xffffffffu, sum1, 1);
                sum1 += __shfl_xor_sync(0xffffffffu, sum1, 2);

                float al0 = exp2f(mprev[mt][0] - mn0);
                float al1 = exp2f(mprev[mt][1] - mn1);
                lrun[mt][0] = lrun[mt][0] * al0 + sum0;
                lrun[mt][1] = lrun[mt][1] * al1 + sum1;
                mprev[mt][0] = mn0;
                mprev[mt][1] = mn1;
#pragma unroll
                for (int nt = 0; nt < 8; nt++) {
                    o[mt][nt][0] *= al0;
                    o[mt][nt][1] *= al0;
                    o[mt][nt][2] *= al1;
                    o[mt][nt][3] *= al1;
                }

                // write P tile (per-warp private smem), tf32, STS.64 pairs
#pragma unroll
                for (int nt = 0; nt < 8; nt++) {
                    *(uint2*)&Pw[(mt * 16 + g)     * FSTR + nt * 8 + q * 2] =
                        make_uint2(f2tf32(s[mt][nt][0]), f2tf32(s[mt][nt][1]));
                    *(uint2*)&Pw[(mt * 16 + g + 8) * FSTR + nt * 8 + q * 2] =
                        make_uint2(f2tf32(s[mt][nt][2]), f2tf32(s[mt][nt][3]));
                }
            }
            __syncwarp();

            // ---- O += P @ V ----
#pragma unroll
            for (int ks = 0; ks < 8; ks++) {
                uint32_t afr[2][4];
#pragma unroll
                for (int mt = 0; mt < 2; mt++) {
                    afr[mt][0] = Pw[(mt * 16 + g)     * FSTR + ks * 8 + q];
                    afr[mt][1] = Pw[(mt * 16 + g + 8) * FSTR + ks * 8 + q];
                    afr[mt][2] = Pw[(mt * 16 + g)     * FSTR + ks * 8 + q + 4];
                    afr[mt][3] = Pw[(mt * 16 + g + 8) * FSTR + ks * 8 + q + 4];
                }
#pragma unroll
                for (int nt = 0; nt < 8; nt++) {
                    uint32_t bfr[2];
                    bfr[0] = Vs[(nt * 8 + g) * FSTR + ks * 8 + q];
                    bfr[1] = Vs[(nt * 8 + g) * FSTR + ks * 8 + q + 4];
                    mma_tf32(o[0][nt], afr[0], bfr);
                    mma_tf32(o[1][nt], afr[1], bfr);
                }
            }
        }

        // ---- epilogue: normalize, store [b, row, h*64 + d] ----
#pragma unroll
        for (int mt = 0; mt < 2; mt++) {
            float inv0 = 1.f / lrun[mt][0];
            float inv1 = 1.f / lrun[mt][1];
            int r0 = q0 + w * 32 + mt * 16 + g;
#pragma unroll
            for (int nt = 0; nt < 8; nt++) {
                int c = h * DH + nt * 8 + q * 2;
                *(float2*)&attn_out[(size_t)(b * SEQ + r0) * DIM + c] =
                    make_float2(o[mt][nt][0] * inv0, o[mt][nt][1] * inv0);
                *(float2*)&attn_out[(size_t)(b * SEQ + r0 + 8) * DIM + c] =
                    make_float2(o[mt][nt][2] * inv1, o[mt][nt][3] * inv1);
            }
        }
    }
}

// ---------------------------------------------------------------------------
extern "C" void kernel_launch(void* const* d_in, const int* in_sizes, int n_in,
                              void* d_out, int out_size) {
    const float* x      = (const float*)d_in[0];   // [2,2048,1024]
    const float* w_qkv  = (const float*)d_in[1];   // [1024,3072]
    const float* w_proj = (const float*)d_in[2];   // [1024,1024]
    float* out = (float*)d_out;                    // [2,2048,1024]

    float *qkv_ptr, *attn_ptr;
    cudaGetSymbolAddress((void**)&qkv_ptr, g_qkv);
    cudaGetSymbolAddress((void**)&attn_ptr, g_attn);

    cudaFuncSetAttribute(flash_mma, cudaFuncAttributeMaxDynamicSharedMemorySize,
                         (int)FLASH_SMEM);

    // 1) qkv = x @ w_qkv    [4096,1024]@[1024,3072]
    sgemm_tf32<<<dim3(3 * DIM / GBN, MTOT / GBM), 256>>>(x, w_qkv, qkv_ptr, MTOT, 3 * DIM, DIM);

    // 2) attention (balanced q-tile pairs)
    flash_mma<<<dim3(NQT / 2, BATCH * HEADS), 128, FLASH_SMEM>>>(qkv_ptr, attn_ptr);

    // 3) out = attn @ w_proj [4096,1024]@[1024,1024]
    sgemm_tf32<<<dim3(DIM / GBN, MTOT / GBM), 256>>>(attn_ptr, w_proj, out, MTOT, DIM, DIM);
}

// round 4
// speedup vs baseline: 2.7726x; 1.0007x over previous
#include <cuda_runtime.h>
#include <cuda_bf16.h>
#include <math.h>
#include <stdint.h>

// Problem constants
#define BATCH 2
#define SEQ   2048
#define DIM   1024
#define HEADS 16
#define DH    64
#define MTOT  (BATCH*SEQ)          // 4096 rows

// Scratch (allocation-free rule: __device__ globals)
__device__ float g_qkv[(size_t)MTOT * 3 * DIM];   // [4096, 3072]
__device__ float g_attn[(size_t)MTOT * DIM];      // [4096, 1024]

__device__ __forceinline__ uint32_t f2tf32(float v) {
    uint32_t o;
    asm("cvt.rna.tf32.f32 %0, %1;" : "=r"(o) : "f"(v));
    return o;
}

__device__ __forceinline__ void mma_tf32(float c[4], const uint32_t a[4], const uint32_t b[2]) {
    asm volatile(
        "mma.sync.aligned.m16n8k8.row.col.f32.tf32.tf32.f32 "
        "{%0,%1,%2,%3}, {%4,%5,%6,%7}, {%8,%9}, {%0,%1,%2,%3};"
        : "+f"(c[0]), "+f"(c[1]), "+f"(c[2]), "+f"(c[3])
        : "r"(a[0]), "r"(a[1]), "r"(a[2]), "r"(a[3]), "r"(b[0]), "r"(b[1]));
}

// ---------------------------------------------------------------------------
// TF32 tensor-core GEMM (unchanged from R1): C = A @ B, row-major fp32.
// ---------------------------------------------------------------------------
#define GBM 128
#define GBN 128
#define GBK 16
#define GSTRIDE 20

__global__ __launch_bounds__(256) void sgemm_tf32(const float* __restrict__ A,
                                                  const float* __restrict__ B,
                                                  float* __restrict__ C,
                                                  int M, int N, int K) {
    __shared__ uint32_t As[2][GBM][GSTRIDE];
    __shared__ uint32_t Bs[2][GBN][GSTRIDE];

    const int tid  = threadIdx.x;
    const int lane = tid & 31;
    const int wid  = tid >> 5;
    const int wm   = wid & 3;
    const int wn   = wid >> 2;
    const int g    = lane >> 2;
    const int q    = lane & 3;

    const int m0 = blockIdx.y * GBM;
    const int n0 = blockIdx.x * GBN;

    const int a_row  = tid >> 2;
    const int a_col4 = (tid & 3) * 4;
    const int b_k    = tid >> 4;
    const int b_n4   = (tid & 15) * 4;

    float acc[2][8][4];
#pragma unroll
    for (int i = 0; i < 2; i++)
#pragma unroll
        for (int j = 0; j < 8; j++)
#pragma unroll
            for (int r = 0; r < 4; r++) acc[i][j][r] = 0.f;

    const int ntiles = K / GBK;

    float4 ra[2], rb[2];
#pragma unroll
    for (int i = 0; i < 2; i++) {
        ra[i] = *(const float4*)&A[(size_t)(m0 + a_row + 64 * i) * K + a_col4];
        rb[i] = *(const float4*)&B[(size_t)b_k * N + n0 + b_n4 + 64 * i];
    }
#pragma unroll
    for (int i = 0; i < 2; i++) {
        int r = a_row + 64 * i;
        As[0][r][a_col4 + 0] = f2tf32(ra[i].x);
        As[0][r][a_col4 + 1] = f2tf32(ra[i].y);
        As[0][r][a_col4 + 2] = f2tf32(ra[i].z);
        As[0][r][a_col4 + 3] = f2tf32(ra[i].w);
        int n = b_n4 + 64 * i;
        Bs[0][n + 0][b_k] = f2tf32(rb[i].x);
        Bs[0][n + 1][b_k] = f2tf32(rb[i].y);
        Bs[0][n + 2][b_k] = f2tf32(rb[i].z);
        Bs[0][n + 3][b_k] = f2tf32(rb[i].w);
    }
    __syncthreads();

    for (int kt = 0; kt < ntiles; kt++) {
        const int cur = kt & 1, nxt = cur ^ 1;
        const bool more = (kt + 1 < ntiles);

        if (more) {
            int k0 = (kt + 1) * GBK;
#pragma unroll
            for (int i = 0; i < 2; i++) {
                ra[i] = *(const float4*)&A[(size_t)(m0 + a_row + 64 * i) * K + k0 + a_col4];
                rb[i] = *(const float4*)&B[(size_t)(k0 + b_k) * N + n0 + b_n4 + 64 * i];
            }
        }

#pragma unroll
        for (int ks = 0; ks < 2; ks++) {
            uint32_t afr[2][4];
#pragma unroll
            for (int mt = 0; mt < 2; mt++) {
                int rb0 = wm * 32 + mt * 16;
                afr[mt][0] = As[cur][rb0 + g][ks * 8 + q];
                afr[mt][1] = As[cur][rb0 + g + 8][ks * 8 + q];
                afr[mt][2] = As[cur][rb0 + g][ks * 8 + q + 4];
                afr[mt][3] = As[cur][rb0 + g + 8][ks * 8 + q + 4];
            }
#pragma unroll
            for (int nt = 0; nt < 8; nt++) {
                int nb = wn * 64 + nt * 8;
                uint32_t bfr[2];
                bfr[0] = Bs[cur][nb + g][ks * 8 + q];
                bfr[1] = Bs[cur][nb + g][ks * 8 + q + 4];
                mma_tf32(acc[0][nt], afr[0], bfr);
                mma_tf32(acc[1][nt], afr[1], bfr);
            }
        }

        if (more) {
#pragma unroll
            for (int i = 0; i < 2; i++) {
                int r = a_row + 64 * i;
                As[nxt][r][a_col4 + 0] = f2tf32(ra[i].x);
                As[nxt][r][a_col4 + 1] = f2tf32(ra[i].y);
                As[nxt][r][a_col4 + 2] = f2tf32(ra[i].z);
                As[nxt][r][a_col4 + 3] = f2tf32(ra[i].w);
                int n = b_n4 + 64 * i;
                Bs[nxt][n + 0][b_k] = f2tf32(rb[i].x);
                Bs[nxt][n + 1][b_k] = f2tf32(rb[i].y);
                Bs[nxt][n + 2][b_k] = f2tf32(rb[i].z);
                Bs[nxt][n + 3][b_k] = f2tf32(rb[i].w);
            }
        }
        __syncthreads();
    }

#pragma unroll
    for (int mt = 0; mt < 2; mt++) {
        int r0 = m0 + wm * 32 + mt * 16 + g;
#pragma unroll
        for (int nt = 0; nt < 8; nt++) {
            int c0 = n0 + wn * 64 + nt * 8 + q * 2;
            *(float2*)&C[(size_t)r0 * N + c0]       = make_float2(acc[mt][nt][0], acc[mt][nt][1]);
            *(float2*)&C[(size_t)(r0 + 8) * N + c0] = make_float2(acc[mt][nt][2], acc[mt][nt][3]);
        }
    }
}

// ---------------------------------------------------------------------------
// Flash attention with TF32 mma.sync tensor cores.
// Block: 128 threads (4 warps) handles the q-tile PAIR {qi, 15-qi} for one
// (b,h) -> perfectly balanced causal work (34 key-tiles per block).
// Each warp: 32 q-rows x 64 keys. Softmax in mma C-fragment layout, base-2.
// Smem: Qs[128][68] tf32, Ks[64][68] (key-major), Vs[64][68] (d-major,
// i.e. V transposed), Ps[4][32][68] per-warp P tiles.
// ---------------------------------------------------------------------------
#define FSTR 68
#define NQT  (SEQ/128)   // 16 q-tiles
#define FLASH_SMEM ((128*FSTR + 64*FSTR + 64*FSTR + 4*32*FSTR) * 4)

__global__ __launch_bounds__(128) void flash_mma(const float* __restrict__ qkv,
                                                 float* __restrict__ attn_out) {
    extern __shared__ uint32_t sm[];
    uint32_t* Qs = sm;                       // [qrow][d]
    uint32_t* Ks = Qs + 128 * FSTR;          // [key][d]
    uint32_t* Vs = Ks + 64 * FSTR;           // [d][key]  (V^T)
    uint32_t* Ps = Vs + 64 * FSTR;           // [warp][row][key]

    const int tid  = threadIdx.x;
    const int lane = tid & 31;
    const int w    = tid >> 5;
    const int g    = lane >> 2;
    const int q    = lane & 3;

    const int bh = blockIdx.y;
    const int b  = bh >> 4;
    const int h  = bh & 15;

    const float LOG2E  = 1.44269504088896f;
    const float scale2 = 0.125f * LOG2E;                       // Dh^-0.5 * log2(e)
    const float slope2 = exp2f(-0.5f * (float)(h + 1)) * LOG2E;

    const float* qb = qkv + (size_t)b * SEQ * (3 * DIM) + h * DH;
    const float* kb = qb + DIM;
    const float* vb = qb + 2 * DIM;

    uint32_t* Pw = Ps + w * 32 * FSTR;

#pragma unroll 1
    for (int half = 0; half < 2; half++) {
        const int qi = half ? (NQT - 1 - blockIdx.x) : blockIdx.x;
        const int q0 = qi * 128;

        __syncthreads();   // Qs/Ks/Vs reuse across halves

        // ---- load Q tile (rows q0..q0+127) as tf32, [row][d] ----
        {
            int r  = tid >> 4;
            int d4 = (tid & 15) * 4;
#pragma unroll
            for (int it = 0; it < 16; it++, r += 8) {
                float4 v = *(const float4*)&qb[(size_t)(q0 + r) * (3 * DIM) + d4];
                *(uint4*)&Qs[r * FSTR + d4] =
                    make_uint4(f2tf32(v.x), f2tf32(v.y), f2tf32(v.z), f2tf32(v.w));
            }
        }

        // per-row state (rows: mt*16+g and mt*16+g+8 within warp tile)
        float o[2][8][4];
        float mprev[2][2], lrun[2][2];
#pragma unroll
        for (int mt = 0; mt < 2; mt++) {
            mprev[mt][0] = mprev[mt][1] = -1e30f;
            lrun[mt][0]  = lrun[mt][1]  = 0.f;
#pragma unroll
            for (int nt = 0; nt < 8; nt++)
#pragma unroll
                for (int r = 0; r < 4; r++) o[mt][nt][r] = 0.f;
        }

        const int nkt = 2 * qi + 2;
        const int wrow_min = q0 + w * 32;       // warp's first q-row
        const int wrow_max = wrow_min + 31;

        for (int kt = 0; kt < nkt; kt++) {
            const int k0 = kt * 64;
            __syncthreads();   // previous tile's PV reads done

            // ---- load K [key][d] and V^T [d][key] ----
            {
                int key = tid >> 4;
                int d4  = (tid & 15) * 4;
#pragma unroll
                for (int it = 0; it < 8; it++, key += 8) {
                    float4 kv = *(const float4*)&kb[(size_t)(k0 + key) * (3 * DIM) + d4];
                    *(uint4*)&Ks[key * FSTR + d4] =
                        make_uint4(f2tf32(kv.x), f2tf32(kv.y), f2tf32(kv.z), f2tf32(kv.w));
                    float4 vv = *(const float4*)&vb[(size_t)(k0 + key) * (3 * DIM) + d4];
                    Vs[(d4 + 0) * FSTR + key] = f2tf32(vv.x);
                    Vs[(d4 + 1) * FSTR + key] = f2tf32(vv.y);
                    Vs[(d4 + 2) * FSTR + key] = f2tf32(vv.z);
                    Vs[(d4 + 3) * FSTR + key] = f2tf32(vv.w);
                }
            }
            __syncthreads();

            // warp-uniform skip: entire tile above the diagonal for this warp
            if (k0 > wrow_max) continue;

            // ---- S = Q @ K^T ----
            float s[2][8][4];
#pragma unroll
            for (int mt = 0; mt < 2; mt++)
#pragma unroll
                for (int nt = 0; nt < 8; nt++)
#pragma unroll
                    for (int r = 0; r < 4; r++) s[mt][nt][r] = 0.f;

#pragma unroll
            for (int ks = 0; ks < 8; ks++) {
                uint32_t afr[2][4];
#pragma unroll
                for (int mt = 0; mt < 2; mt++) {
                    int rb0 = w * 32 + mt * 16;
                    afr[mt][0] = Qs[(rb0 + g)     * FSTR + ks * 8 + q];
                    afr[mt][1] = Qs[(rb0 + g + 8) * FSTR + ks * 8 + q];
                    afr[mt][2] = Qs[(rb0 + g)     * FSTR + ks * 8 + q + 4];
                    afr[mt][3] = Qs[(rb0 + g + 8) * FSTR + ks * 8 + q + 4];
                }
#pragma unroll
                for (int nt = 0; nt < 8; nt++) {
                    uint32_t bfr[2];
                    bfr[0] = Ks[(nt * 8 + g) * FSTR + ks * 8 + q];
                    bfr[1] = Ks[(nt * 8 + g) * FSTR + ks * 8 + q + 4];
                    mma_tf32(s[0][nt], afr[0], bfr);
                    mma_tf32(s[1][nt], afr[1], bfr);
                }
            }

            // ---- bias + mask + online softmax (base-2 domain) ----
            const bool need_mask = (k0 + 63 > wrow_min);
#pragma unroll
            for (int mt = 0; mt < 2; mt++) {
                const int r0 = wrow_min + mt * 16 + g;
                const int r1 = r0 + 8;
                float mx0 = -1e30f, mx1 = -1e30f;
#pragma unroll
                for (int nt = 0; nt < 8; nt++) {
#pragma unroll
                    for (int jj = 0; jj < 2; jj++) {
                        int col = k0 + nt * 8 + q * 2 + jj;
                        float bias = slope2 * (float)col;
                        float v0 = fmaf(s[mt][nt][jj],     scale2, bias);
                        float v1 = fmaf(s[mt][nt][2 + jj], scale2, bias);
                        if (need_mask) {
                            if (col > r0) v0 = -1e30f;
                            if (col > r1) v1 = -1e30f;
                        }
                        s[mt][nt][jj]     = v0;
                        s[mt][nt][2 + jj] = v1;
                        mx0 = fmaxf(mx0, v0);
                        mx1 = fmaxf(mx1, v1);
                    }
                }
                mx0 = fmaxf(mx0, __shfl_xor_sync(0xffffffffu, mx0, 1));
                mx0 = fmaxf(mx0, __shfl_xor_sync(0xffffffffu, mx0, 2));
                mx1 = fmaxf(mx1, __shfl_xor_sync(0xffffffffu, mx1, 1));
                mx1 = fmaxf(mx1, __shfl_xor_sync(0xffffffffu, mx1, 2));

                float mn0 = fmaxf(mprev[mt][0], mx0);
                float mn1 = fmaxf(mprev[mt][1], mx1);
                float sum0 = 0.f, sum1 = 0.f;
#pragma unroll
                for (int nt = 0; nt < 8; nt++) {
#pragma unroll
                    for (int jj = 0; jj < 2; jj++) {
                        float p0 = exp2f(s[mt][nt][jj]     - mn0);
                        float p1 = exp2f(s[mt][nt][2 + jj] - mn1);
                        s[mt][nt][jj]     = p0;
                        s[mt][nt][2 + jj] = p1;
                        sum0 += p0;
                        sum1 += p1;
                    }
                }
                sum0 += __shfl_xor_sync(0xffffffffu, sum0, 1);
                sum0 += __shfl_xor_sync(0xffffffffu, sum0, 2);
                sum1 += __shfl_xor_sync(0xffffffffu, sum1, 1);
                sum1 += __shfl_xor_sync(0xffffffffu, sum1, 2);

                float al0 = exp2f(mprev[mt][0] - mn0);
                float al1 = exp2f(mprev[mt][1] - mn1);
                lrun[mt][0] = lrun[mt][0] * al0 + sum0;
                lrun[mt][1] = lrun[mt][1] * al1 + sum1;
                mprev[mt][0] = mn0;
                mprev[mt][1] = mn1;
#pragma unroll
                for (int nt = 0; nt < 8; nt++) {
                    o[mt][nt][0] *= al0;
                    o[mt][nt][1] *= al0;
                    o[mt][nt][2] *= al1;
                    o[mt][nt][3] *= al1;
                }

                // write P tile (per-warp private smem), tf32, STS.64 pairs
#pragma unroll
                for (int nt = 0; nt < 8; nt++) {
                    *(uint2*)&Pw[(mt * 16 + g)     * FSTR + nt * 8 + q * 2] =
                        make_uint2(f2tf32(s[mt][nt][0]), f2tf32(s[mt][nt][1]));
                    *(uint2*)&Pw[(mt * 16 + g + 8) * FSTR + nt * 8 + q * 2] =
                        make_uint2(f2tf32(s[mt][nt][2]), f2tf32(s[mt][nt][3]));
                }
            }
            __syncwarp();

            // ---- O += P @ V ----
#pragma unroll
            for (int ks = 0; ks < 8; ks++) {
                uint32_t afr[2][4];
#pragma unroll
                for (int mt = 0; mt < 2; mt++) {
                    afr[mt][0] = Pw[(mt * 16 + g)     * FSTR + ks * 8 + q];
                    afr[mt][1] = Pw[(mt * 16 + g + 8) * FSTR + ks * 8 + q];
                    afr[mt][2] = Pw[(mt * 16 + g)     * FSTR + ks * 8 + q + 4];
                    afr[mt][3] = Pw[(mt * 16 + g + 8) * FSTR + ks * 8 + q + 4];
                }
#pragma unroll
                for (int nt = 0; nt < 8; nt++) {
                    uint32_t bfr[2];
                    bfr[0] = Vs[(nt * 8 + g) * FSTR + ks * 8 + q];
                    bfr[1] = Vs[(nt * 8 + g) * FSTR + ks * 8 + q + 4];
                    mma_tf32(o[0][nt], afr[0], bfr);
                    mma_tf32(o[1][nt], afr[1], bfr);
                }
            }
        }

        // ---- epilogue: normalize, store [b, row, h*64 + d] ----
#pragma unroll
        for (int mt = 0; mt < 2; mt++) {
            float inv0 = 1.f / lrun[mt][0];
            float inv1 = 1.f / lrun[mt][1];
            int r0 = q0 + w * 32 + mt * 16 + g;
#pragma unroll
            for (int nt = 0; nt < 8; nt++) {
                int c = h * DH + nt * 8 + q * 2;
                *(float2*)&attn_out[(size_t)(b * SEQ + r0) * DIM + c] =
                    make_float2(o[mt][nt][0] * inv0, o[mt][nt][1] * inv0);
                *(float2*)&attn_out[(size_t)(b * SEQ + r0 + 8) * DIM + c] =
                    make_float2(o[mt][nt][2] * inv1, o[mt][nt][3] * inv1);
            }
        }
    }
}

// ---------------------------------------------------------------------------
extern "C" void kernel_launch(void* const* d_in, const int* in_sizes, int n_in,
                              void* d_out, int out_size) {
    const float* x      = (const float*)d_in[0];   // [2,2048,1024]
    const float* w_qkv  = (const float*)d_in[1];   // [1024,3072]
    const float* w_proj = (const float*)d_in[2];   // [1024,1024]
    float* out = (float*)d_out;                    // [2,2048,1024]

    float *qkv_ptr, *attn_ptr;
    cudaGetSymbolAddress((void**)&qkv_ptr, g_qkv);
    cudaGetSymbolAddress((void**)&attn_ptr, g_attn);

    cudaFuncSetAttribute(flash_mma, cudaFuncAttributeMaxDynamicSharedMemorySize,
                         (int)FLASH_SMEM);

    // 1) qkv = x @ w_qkv    [4096,1024]@[1024,3072]
    sgemm_tf32<<<dim3(3 * DIM / GBN, MTOT / GBM), 256>>>(x, w_qkv, qkv_ptr, MTOT, 3 * DIM, DIM);

    // 2) attention (balanced q-tile pairs)
    flash_mma<<<dim3(NQT / 2, BATCH * HEADS), 128, FLASH_SMEM>>>(qkv_ptr, attn_ptr);

    // 3) out = attn @ w_proj [4096,1024]@[1024,1024]
    sgemm_tf32<<<dim3(DIM / GBN, MTOT / GBM), 256>>>(attn_ptr, w_proj, out, MTOT, DIM, DIM);
}